// round 10
// baseline (speedup 1.0000x reference)
#include <cuda_runtime.h>
#include <cuda_fp16.h>
#include <math.h>

#define NN   100000
#define NE   1600000
#define INF  64
#define HIDD 128
#define NCLS 10
#define NB   ((NN + 255) / 256)     // 391 scan blocks
#define FULL 0xffffffffu

// packed f32x2 helpers
__device__ __forceinline__ unsigned long long f2pk(float lo, float hi) {
    unsigned long long r;
    asm("mov.b64 %0, {%1, %2};" : "=l"(r) : "f"(lo), "f"(hi));
    return r;
}
__device__ __forceinline__ void ffma2(unsigned long long& d,
                                      unsigned long long a,
                                      unsigned long long b) {
    asm("fma.rn.f32x2 %0, %1, %2, %0;" : "+l"(d) : "l"(a), "l"(b));
}
__device__ __forceinline__ float2 f2unpk(unsigned long long v) {
    float lo, hi;
    asm("mov.b64 {%0, %1}, %2;" : "=f"(lo), "=f"(hi) : "l"(v));
    return make_float2(lo, hi);
}

// ---------------- scratch (no allocations allowed) ----------------
__device__ int   g_is64;
__device__ int   g_cnt[NN];
__device__ int   g_cur[NN];
__device__ int   g_offs[NN];          // block-local exclusive scan
__device__ int   g_bsum[NB];
__device__ int   g_bpre[NB];
__device__ float g_dinv[NN];
__device__ int   g_rows[NE];
__device__ int   g_cols[NE];
__device__ int   g_msrc[NE];          // 6.4 MB : CSR src per slot
__device__ __half2 g_xh[NN * 32];     // 12.8 MB : xs = dinv*x in half
__device__ float4 g_agg1[NN * (INF / 4)];   // 25.6 MB
__device__ __half g_t2sh[NN * 16];          // 3.2 MB : dinv*(h@W2) as half, 32B rows

// ---------------- kernels ----------------

__global__ void k_init(const void* __restrict__ ei_raw, float* __restrict__ out) {
    __shared__ int s_nz;
    int tid = threadIdx.x;
    int i = blockIdx.x * blockDim.x + tid;
    if (i < NN) { g_cnt[i] = 0; g_cur[i] = 0; }
    if (i < NCLS) out[i] = 0.0f;
    if (tid == 0) s_nz = 0;
    __syncthreads();
    if (blockIdx.x == 0) {
        const unsigned int* w = (const unsigned int*)ei_raw;
        if (w[tid * 2 + 1] != 0u) atomicAdd(&s_nz, 1);
    }
    __syncthreads();
    if (blockIdx.x == 0 && tid == 0) g_is64 = (s_nz == 0) ? 1 : 0;
}

__global__ void k_edges_degree(const void* __restrict__ ei_raw) {
    int e = blockIdx.x * blockDim.x + threadIdx.x;
    if (e >= NE) return;
    int r, c;
    if (g_is64) {
        const long long* ei = (const long long*)ei_raw;
        r = (int)ei[e];  c = (int)ei[NE + e];
    } else {
        const int* ei = (const int*)ei_raw;
        r = ei[e];       c = ei[NE + e];
    }
    r = min(max(r, 0), NN - 1);
    c = min(max(c, 0), NN - 1);
    g_rows[e] = r;
    g_cols[e] = c;
    atomicAdd(&g_cnt[c], 1);
}

__global__ void k_scanA() {
    __shared__ int s[256];
    int tid = threadIdx.x;
    int i = blockIdx.x * 256 + tid;
    int v = (i < NN) ? g_cnt[i] : 0;
    if (i < NN) g_dinv[i] = rsqrtf((float)(v + 1));
    s[tid] = v;
    __syncthreads();
    #pragma unroll
    for (int st = 1; st < 256; st <<= 1) {
        int t = (tid >= st) ? s[tid - st] : 0;
        __syncthreads();
        s[tid] += t;
        __syncthreads();
    }
    if (i < NN) g_offs[i] = s[tid] - v;
    if (tid == 255) g_bsum[blockIdx.x] = s[255];
}

__global__ void k_scanB() {
    __shared__ int s[512];
    int tid = threadIdx.x;
    int v = (tid < NB) ? g_bsum[tid] : 0;
    s[tid] = v;
    __syncthreads();
    #pragma unroll
    for (int st = 1; st < 512; st <<= 1) {
        int t = (tid >= st) ? s[tid - st] : 0;
        __syncthreads();
        s[tid] += t;
        __syncthreads();
    }
    if (tid < NB) g_bpre[tid] = s[tid] - v;
}

__global__ void k_xhalf(const float* __restrict__ x) {
    int i = blockIdx.x * blockDim.x + threadIdx.x;   // NN*32
    if (i < NN * 32) {
        int node = i >> 5;
        float d = g_dinv[node];
        float2 v = ((const float2*)x)[i];
        g_xh[i] = __floats2half2_rn(d * v.x, d * v.y);
    }
}

__global__ void k_fill() {
    int e = blockIdx.x * blockDim.x + threadIdx.x;
    if (e >= NE) return;
    int c = g_cols[e];
    int pos = g_offs[c] + g_bpre[c >> 8] + atomicAdd(&g_cur[c], 1);
    g_msrc[pos] = g_rows[e];
}

// layer-1 aggregation: warp per dest node, shfl-chunked meta, MLP=4
__global__ void k_gather1() {
    int wid  = (blockIdx.x * blockDim.x + threadIdx.x) >> 5;
    int lane = threadIdx.x & 31;
    if (wid >= NN) return;
    int d = wid;
    float2 acc = __half22float2(g_xh[d * 32 + lane]);   // self term xs[d]
    float2 acc2 = make_float2(0.f, 0.f);
    int beg = g_offs[d] + g_bpre[d >> 8];
    int deg = g_cnt[d];
    for (int base = 0; base < deg; base += 32) {
        int rem = deg - base;
        int cnt = rem < 32 ? rem : 32;
        int m = (lane < cnt) ? g_msrc[beg + base + lane] : 0;
        int j = 0;
        for (; j + 4 <= cnt; j += 4) {
            int s0 = __shfl_sync(FULL, m, j);
            int s1 = __shfl_sync(FULL, m, j + 1);
            int s2 = __shfl_sync(FULL, m, j + 2);
            int s3 = __shfl_sync(FULL, m, j + 3);
            float2 f0 = __half22float2(g_xh[s0 * 32 + lane]);
            float2 f1 = __half22float2(g_xh[s1 * 32 + lane]);
            float2 f2 = __half22float2(g_xh[s2 * 32 + lane]);
            float2 f3 = __half22float2(g_xh[s3 * 32 + lane]);
            acc.x  += f0.x + f1.x;  acc.y  += f0.y + f1.y;
            acc2.x += f2.x + f3.x;  acc2.y += f2.y + f3.y;
        }
        for (; j < cnt; j++) {
            int src = __shfl_sync(FULL, m, j);
            float2 v = __half22float2(g_xh[src * 32 + lane]);
            acc.x += v.x;  acc.y += v.y;
        }
    }
    float dd = g_dinv[d];
    acc.x = (acc.x + acc2.x) * dd;
    acc.y = (acc.y + acc2.y) * dd;
    ((float2*)g_agg1)[d * 32 + lane] = acc;
}

// fused gemm: h = relu(agg1@W1+b1) in smem; t2sh = half(dinv*(h@W2))
// A-tile stored TRANSPOSED (stride 66) so a-operands are vector LDS.64 broadcasts.
__global__ void k_gemm12(const float* __restrict__ W1, const float* __restrict__ b1,
                         const float* __restrict__ W2) {
    __shared__ float As[64 * 66];        // A^T tile : As[k*66 + m]; later W2 (1280 floats)
    __shared__ float Bs[64 * 132];       // W1 [64][128] contiguous; later h tile stride 132
    int tid = threadIdx.x;
    int bnode = blockIdx.x * 64;

    for (int t = tid; t < (64 * 128) / 4; t += 256)
        ((float4*)Bs)[t] = ((const float4*)W1)[t];
    for (int t = tid; t < 64 * 16; t += 256) {
        int lr = t >> 4, q = t & 15;
        int node = bnode + lr;
        float4 v = (node < NN) ? g_agg1[node * 16 + q]
                               : make_float4(0.f, 0.f, 0.f, 0.f);
        As[(4 * q + 0) * 66 + lr] = v.x;
        As[(4 * q + 1) * 66 + lr] = v.y;
        As[(4 * q + 2) * 66 + lr] = v.z;
        As[(4 * q + 3) * 66 + lr] = v.w;
    }
    __syncthreads();

    int tx = tid & 31, ty = tid >> 5;
    unsigned long long acc[4][4];        // [m-pair][n] ; rows ty*8+2p, ty*8+2p+1
    #pragma unroll
    for (int p = 0; p < 4; p++)
        #pragma unroll
        for (int n = 0; n < 4; n++) acc[p][n] = 0ull;

    #pragma unroll 4
    for (int k = 0; k < 64; k++) {
        float4 bb = ((const float4*)Bs)[k * 32 + tx];
        const unsigned long long* ap =
            (const unsigned long long*)&As[k * 66 + ty * 8];
        unsigned long long a0 = ap[0], a1 = ap[1], a2 = ap[2], a3 = ap[3];
        unsigned long long bx = f2pk(bb.x, bb.x);
        unsigned long long by = f2pk(bb.y, bb.y);
        unsigned long long bz = f2pk(bb.z, bb.z);
        unsigned long long bw = f2pk(bb.w, bb.w);
        ffma2(acc[0][0], a0, bx); ffma2(acc[0][1], a0, by);
        ffma2(acc[0][2], a0, bz); ffma2(acc[0][3], a0, bw);
        ffma2(acc[1][0], a1, bx); ffma2(acc[1][1], a1, by);
        ffma2(acc[1][2], a1, bz); ffma2(acc[1][3], a1, bw);
        ffma2(acc[2][0], a2, bx); ffma2(acc[2][1], a2, by);
        ffma2(acc[2][2], a2, bz); ffma2(acc[2][3], a2, bw);
        ffma2(acc[3][0], a3, bx); ffma2(acc[3][1], a3, by);
        ffma2(acc[3][2], a3, bz); ffma2(acc[3][3], a3, bw);
    }
    __syncthreads();   // done reading As/Bs

    // write h tile (relu+bias) to Bs stride 132; W2 -> As
    float4 bias = ((const float4*)b1)[tx];
    #pragma unroll
    for (int p = 0; p < 4; p++) {
        #pragma unroll
        for (int n = 0; n < 4; n++) {
            float2 pv = f2unpk(acc[p][n]);
            float bn = (n == 0) ? bias.x : (n == 1) ? bias.y : (n == 2) ? bias.z : bias.w;
            Bs[(ty * 8 + 2 * p    ) * 132 + tx * 4 + n] = fmaxf(pv.x + bn, 0.0f);
            Bs[(ty * 8 + 2 * p + 1) * 132 + tx * 4 + n] = fmaxf(pv.y + bn, 0.0f);
        }
    }
    for (int t = tid; t < HIDD * NCLS; t += 256) As[t] = W2[t];
    __syncthreads();

    // t2sh for the 64 nodes: 640 outputs over 256 threads
    for (int o = tid; o < 64 * NCLS; o += 256) {
        int ln = o / NCLS, c = o - ln * NCLS;
        int node = bnode + ln;
        if (node < NN) {
            const float* h = &Bs[ln * 132];
            float s = 0.0f;
            #pragma unroll 8
            for (int k = 0; k < HIDD; k++) s = fmaf(h[k], As[k * NCLS + c], s);
            g_t2sh[node * 16 + c] = __float2half(g_dinv[node] * s);
        }
    }
}

// fused layer-2: lane-per-edge gather over 32B half rows + warp log-softmax + reduce
__global__ void k_gather2f(const float* __restrict__ b2, float* __restrict__ out) {
    __shared__ float sacc[NCLS];
    int tid = threadIdx.x;
    if (tid < NCLS) sacc[tid] = 0.0f;
    __syncthreads();
    int wid  = (blockIdx.x * blockDim.x + tid) >> 5;
    int lane = tid & 31;
    if (wid < NN) {
        int d = wid;
        float2 a01 = make_float2(0.f, 0.f), a23 = a01, a45 = a01, a67 = a01, a89 = a01;
        int beg = g_offs[d] + g_bpre[d >> 8];
        int deg = g_cnt[d];
        for (int p = lane; p < deg; p += 32) {
            int src = g_msrc[beg + p];
            uint4 u = *(const uint4*)&g_t2sh[src * 16];       // halfs 0..7 (16B aligned)
            unsigned int w = *(const unsigned int*)&g_t2sh[src * 16 + 8]; // halfs 8..9
            float2 f;
            f = __half22float2(*reinterpret_cast<__half2*>(&u.x)); a01.x += f.x; a01.y += f.y;
            f = __half22float2(*reinterpret_cast<__half2*>(&u.y)); a23.x += f.x; a23.y += f.y;
            f = __half22float2(*reinterpret_cast<__half2*>(&u.z)); a45.x += f.x; a45.y += f.y;
            f = __half22float2(*reinterpret_cast<__half2*>(&u.w)); a67.x += f.x; a67.y += f.y;
            f = __half22float2(*reinterpret_cast<__half2*>(&w));   a89.x += f.x; a89.y += f.y;
        }
        float vals[10] = {a01.x, a01.y, a23.x, a23.y, a45.x,
                          a45.y, a67.x, a67.y, a89.x, a89.y};
        float keep = 0.0f;
        #pragma unroll
        for (int c = 0; c < 10; c++) {
            float s = vals[c];
            #pragma unroll
            for (int o = 16; o; o >>= 1) s += __shfl_xor_sync(FULL, s, o);
            if (lane == c) keep = s;
        }
        float v = 0.0f;
        if (lane < 10) {
            float dd = g_dinv[d];
            v = dd * (keep + __half2float(g_t2sh[d * 16 + lane])) + b2[lane];
        }
        float mv = (lane < 10) ? v : -1e30f;
        #pragma unroll
        for (int o = 16; o; o >>= 1) mv = fmaxf(mv, __shfl_xor_sync(FULL, mv, o));
        float ex = (lane < 10) ? expf(v - mv) : 0.0f;
        float sm = ex;
        #pragma unroll
        for (int o = 16; o; o >>= 1) sm += __shfl_xor_sync(FULL, sm, o);
        float lse = mv + logf(sm);
        if (lane < 10) atomicAdd(&sacc[lane], v - lse);
    }
    __syncthreads();
    if (tid < NCLS) atomicAdd(&out[tid], sacc[tid] * (1.0f / (float)NN));
}

// ---------------- launch ----------------
extern "C" void kernel_launch(void* const* d_in, const int* in_sizes, int n_in,
                              void* d_out, int out_size) {
    const float* x  = (const float*)d_in[0];
    const void*  ei = d_in[1];
    const float* W1 = (const float*)d_in[2];
    const float* b1 = (const float*)d_in[3];
    const float* W2 = (const float*)d_in[4];
    const float* b2 = (const float*)d_in[5];
    float* out = (float*)d_out;

    k_init        <<<(NN + 255) / 256, 256>>>(ei, out);
    k_edges_degree<<<(NE + 255) / 256, 256>>>(ei);
    k_scanA       <<<NB, 256>>>();
    k_scanB       <<<1, 512>>>();
    k_xhalf       <<<(NN * 32 + 255) / 256, 256>>>(x);
    k_fill        <<<(NE + 255) / 256, 256>>>();
    k_gather1     <<<(NN * 32 + 255) / 256, 256>>>();
    k_gemm12      <<<(NN + 63) / 64, 256>>>(W1, b1, W2);
    k_gather2f    <<<(NN * 32 + 511) / 512, 512>>>(b2, out);
}

// round 11
// speedup vs baseline: 1.1502x; 1.1502x over previous
#include <cuda_runtime.h>
#include <cuda_fp16.h>
#include <math.h>

#define NN   100000
#define NE   1600000
#define INF  64
#define HIDD 128
#define NCLS 10
#define NCP  12
#define SB   512
#define NBS  ((NN + SB - 1) / SB)    // 196 scan blocks
#define FULL 0xffffffffu

// packed f32x2 helpers
__device__ __forceinline__ unsigned long long f2pk(float lo, float hi) {
    unsigned long long r;
    asm("mov.b64 %0, {%1, %2};" : "=l"(r) : "f"(lo), "f"(hi));
    return r;
}
__device__ __forceinline__ void ffma2(unsigned long long& d,
                                      unsigned long long a,
                                      unsigned long long b) {
    asm("fma.rn.f32x2 %0, %1, %2, %0;" : "+l"(d) : "l"(a), "l"(b));
}
__device__ __forceinline__ float2 f2unpk(unsigned long long v) {
    float lo, hi;
    asm("mov.b64 {%0, %1}, %2;" : "=f"(lo), "=f"(hi) : "l"(v));
    return make_float2(lo, hi);
}

// ---------------- scratch (no allocations allowed) ----------------
__device__ int   g_is64;
__device__ int   g_done;
__device__ int   g_cnt[NN];
__device__ int   g_cur[NN];
__device__ int   g_offs[NN];          // block-local exclusive scan (SB-wide blocks)
__device__ int   g_bsum[NBS];
__device__ int   g_bpre[NBS];
__device__ float g_dinv[NN];
__device__ int   g_msrc[NE];          // 6.4 MB : CSR src per slot
__device__ __half2 g_xh[NN * 32];     // 12.8 MB : xs = dinv*x in half
__device__ float4 g_agg1[NN * (INF / 4)];   // 25.6 MB
__device__ float g_t2s[NN * NCP];           // 4.8 MB : dinv*(h@W2), stride 12

// ---------------- kernels ----------------

// init (cnt, cur, done, out) + dtype sniff (block 0)
__global__ void k_init(const void* __restrict__ ei_raw, float* __restrict__ out) {
    __shared__ int s_nz;
    int tid = threadIdx.x;
    int i = blockIdx.x * blockDim.x + tid;
    if (i < NN) { g_cnt[i] = 0; g_cur[i] = 0; }
    if (i < NCLS) out[i] = 0.0f;
    if (blockIdx.x == 0 && tid == 0) g_done = 0;
    if (tid == 0) s_nz = 0;
    __syncthreads();
    if (blockIdx.x == 0) {
        const unsigned int* w = (const unsigned int*)ei_raw;
        if (w[tid * 2 + 1] != 0u) atomicAdd(&s_nz, 1);
    }
    __syncthreads();
    if (blockIdx.x == 0 && tid == 0) g_is64 = (s_nz == 0) ? 1 : 0;
}

// degree histogram — reads only the col half of edge_index
__global__ void k_degree(const void* __restrict__ ei_raw) {
    int e = blockIdx.x * blockDim.x + threadIdx.x;
    if (e >= NE) return;
    int c;
    if (g_is64) c = (int)((const long long*)ei_raw)[NE + e];
    else        c = ((const int*)ei_raw)[NE + e];
    c = min(max(c, 0), NN - 1);
    atomicAdd(&g_cnt[c], 1);
}

// fused scan: block-local exclusive scan + dinv; last block scans block sums
__global__ void k_scan() {
    __shared__ int s[SB];
    __shared__ int isLast;
    int tid = threadIdx.x;
    int i = blockIdx.x * SB + tid;
    int v = (i < NN) ? g_cnt[i] : 0;
    if (i < NN) g_dinv[i] = rsqrtf((float)(v + 1));
    s[tid] = v;
    __syncthreads();
    #pragma unroll
    for (int st = 1; st < SB; st <<= 1) {
        int t = (tid >= st) ? s[tid - st] : 0;
        __syncthreads();
        s[tid] += t;
        __syncthreads();
    }
    if (i < NN) g_offs[i] = s[tid] - v;
    if (tid == SB - 1) {
        g_bsum[blockIdx.x] = s[SB - 1];
        __threadfence();
        int t = atomicAdd(&g_done, 1);
        isLast = (t == (int)gridDim.x - 1);
    }
    __syncthreads();
    if (isLast) {
        int v2 = (tid < NBS) ? g_bsum[tid] : 0;
        s[tid] = v2;
        __syncthreads();
        #pragma unroll
        for (int st = 1; st < SB; st <<= 1) {
            int t = (tid >= st) ? s[tid - st] : 0;
            __syncthreads();
            s[tid] += t;
            __syncthreads();
        }
        if (tid < NBS) g_bpre[tid] = s[tid] - v2;
    }
}

// fused: CSR fill (decode edge_index directly) + xs = dinv*x -> half
__global__ void k_fillx(const void* __restrict__ ei_raw, const float* __restrict__ x) {
    int i = blockIdx.x * blockDim.x + threadIdx.x;   // NN*32 = 3.2M threads
    if (i < NE) {
        int r, c;
        if (g_is64) {
            const long long* ei = (const long long*)ei_raw;
            r = (int)ei[i];  c = (int)ei[NE + i];
        } else {
            const int* ei = (const int*)ei_raw;
            r = ei[i];       c = ei[NE + i];
        }
        r = min(max(r, 0), NN - 1);
        c = min(max(c, 0), NN - 1);
        int pos = g_offs[c] + g_bpre[c >> 9] + atomicAdd(&g_cur[c], 1);
        g_msrc[pos] = r;
    }
    if (i < NN * 32) {
        int node = i >> 5;
        float d = g_dinv[node];
        float2 v = ((const float2*)x)[i];
        g_xh[i] = __floats2half2_rn(d * v.x, d * v.y);
    }
}

// layer-1 aggregation: warp per dest node, shfl-chunked meta, MLP=4
__global__ void k_gather1() {
    int wid  = (blockIdx.x * blockDim.x + threadIdx.x) >> 5;
    int lane = threadIdx.x & 31;
    if (wid >= NN) return;
    int d = wid;
    float2 acc = __half22float2(g_xh[d * 32 + lane]);   // self term xs[d]
    float2 acc2 = make_float2(0.f, 0.f);
    int beg = g_offs[d] + g_bpre[d >> 9];
    int deg = g_cnt[d];
    for (int base = 0; base < deg; base += 32) {
        int rem = deg - base;
        int cnt = rem < 32 ? rem : 32;
        int m = (lane < cnt) ? g_msrc[beg + base + lane] : 0;
        int j = 0;
        for (; j + 4 <= cnt; j += 4) {
            int s0 = __shfl_sync(FULL, m, j);
            int s1 = __shfl_sync(FULL, m, j + 1);
            int s2 = __shfl_sync(FULL, m, j + 2);
            int s3 = __shfl_sync(FULL, m, j + 3);
            float2 f0 = __half22float2(g_xh[s0 * 32 + lane]);
            float2 f1 = __half22float2(g_xh[s1 * 32 + lane]);
            float2 f2 = __half22float2(g_xh[s2 * 32 + lane]);
            float2 f3 = __half22float2(g_xh[s3 * 32 + lane]);
            acc.x  += f0.x + f1.x;  acc.y  += f0.y + f1.y;
            acc2.x += f2.x + f3.x;  acc2.y += f2.y + f3.y;
        }
        for (; j < cnt; j++) {
            int src = __shfl_sync(FULL, m, j);
            float2 v = __half22float2(g_xh[src * 32 + lane]);
            acc.x += v.x;  acc.y += v.y;
        }
    }
    float dd = g_dinv[d];
    acc.x = (acc.x + acc2.x) * dd;
    acc.y = (acc.y + acc2.y) * dd;
    ((float2*)g_agg1)[d * 32 + lane] = acc;
}

// fused: h = relu(agg1@W1 + b1) [smem only] ; t2s = dinv*(h@W2)   (R9 form)
__global__ void k_gemm12(const float* __restrict__ W1, const float* __restrict__ b1,
                         const float* __restrict__ W2) {
    __shared__ float As[64 * 64];        // A tile / then W2 (1280 floats)
    __shared__ float Bs[64 * 132];       // W1 (64x128) / then h tile stride 132
    int tid = threadIdx.x;
    int bnode = blockIdx.x * 64;

    for (int t = tid; t < (64 * 128) / 4; t += 256)
        ((float4*)Bs)[t] = ((const float4*)W1)[t];
    for (int t = tid; t < 64 * 16; t += 256) {
        int lr = t >> 4, q = t & 15;
        int node = bnode + lr;
        float4 v = (node < NN) ? g_agg1[node * 16 + q]
                               : make_float4(0.f, 0.f, 0.f, 0.f);
        ((float4*)As)[t] = v;
    }
    __syncthreads();

    int tx = tid & 31, ty = tid >> 5;
    unsigned long long a01[8], a23[8];
    #pragma unroll
    for (int i = 0; i < 8; i++) { a01[i] = 0ull; a23[i] = 0ull; }

    #pragma unroll 4
    for (int k = 0; k < 64; k++) {
        float4 bb = ((const float4*)Bs)[k * 32 + tx];
        unsigned long long b01 = f2pk(bb.x, bb.y);
        unsigned long long b23 = f2pk(bb.z, bb.w);
        #pragma unroll
        for (int i = 0; i < 8; i++) {
            float a = As[(ty * 8 + i) * 64 + k];
            unsigned long long aa = f2pk(a, a);
            ffma2(a01[i], aa, b01);
            ffma2(a23[i], aa, b23);
        }
    }
    __syncthreads();

    float4 bias = ((const float4*)b1)[tx];
    #pragma unroll
    for (int i = 0; i < 8; i++) {
        float2 p = f2unpk(a01[i]);
        float2 q = f2unpk(a23[i]);
        float* hrow = &Bs[(ty * 8 + i) * 132 + tx * 4];
        hrow[0] = fmaxf(p.x + bias.x, 0.0f);
        hrow[1] = fmaxf(p.y + bias.y, 0.0f);
        hrow[2] = fmaxf(q.x + bias.z, 0.0f);
        hrow[3] = fmaxf(q.y + bias.w, 0.0f);
    }
    for (int t = tid; t < HIDD * NCLS; t += 256) As[t] = W2[t];
    __syncthreads();

    for (int o = tid; o < 64 * NCLS; o += 256) {
        int ln = o / NCLS, c = o - ln * NCLS;
        int node = bnode + ln;
        if (node < NN) {
            const float* h = &Bs[ln * 132];
            float s = 0.0f;
            #pragma unroll 8
            for (int k = 0; k < HIDD; k++) s = fmaf(h[k], As[k * NCLS + c], s);
            g_t2s[node * NCP + c] = g_dinv[node] * s;
        }
    }
}

// fused: layer-2 gather + bias + self + log_softmax + global mean-reduce (R9 form)
__global__ void k_gather2f(const float* __restrict__ b2, float* __restrict__ out) {
    __shared__ float sacc[NCLS];
    int tid = threadIdx.x;
    if (tid < NCLS) sacc[tid] = 0.0f;
    __syncthreads();
    int wid  = (blockIdx.x * blockDim.x + tid) >> 5;
    int lane = tid & 31;
    if (wid < NN) {
        int d = wid;
        int s = lane / 10;          // 0..2 active
        int c = lane - s * 10;
        float acc = 0.0f, accB = 0.0f;
        int beg = g_offs[d] + g_bpre[d >> 9];
        int deg = g_cnt[d];
        for (int base = 0; base < deg; base += 32) {
            int rem = deg - base;
            int cnt = rem < 32 ? rem : 32;
            int m = (lane < cnt) ? g_msrc[beg + base + lane] : 0;
            int iters = (cnt + 2) / 3;
            int jj = 0;
            for (; jj + 2 <= iters; jj += 2) {
                int j0 = jj * 3 + s;
                int j1 = j0 + 3;
                int s0 = __shfl_sync(FULL, m, j0 < 31 ? j0 : 31);
                int s1 = __shfl_sync(FULL, m, j1 < 31 ? j1 : 31);
                float t0 = 0.f, t1 = 0.f;
                if (s < 3 && j0 < cnt) t0 = g_t2s[s0 * NCP + c];
                if (s < 3 && j1 < cnt) t1 = g_t2s[s1 * NCP + c];
                acc += t0;
                accB += t1;
            }
            for (; jj < iters; jj++) {
                int j = jj * 3 + s;
                int src = __shfl_sync(FULL, m, j < 31 ? j : 31);
                if (s < 3 && j < cnt) acc += g_t2s[src * NCP + c];
            }
        }
        acc += accB;
        float a1 = __shfl_sync(FULL, acc, (lane + 10) & 31);
        float a2 = __shfl_sync(FULL, acc, (lane + 20) & 31);
        float v = 0.0f;
        if (lane < 10) {
            float dd = g_dinv[d];
            v = dd * (acc + a1 + a2 + g_t2s[d * NCP + lane]) + b2[lane];
        }
        float mv = (lane < 10) ? v : -1e30f;
        #pragma unroll
        for (int o = 16; o; o >>= 1) mv = fmaxf(mv, __shfl_xor_sync(FULL, mv, o));
        float ex = (lane < 10) ? expf(v - mv) : 0.0f;
        float sm = ex;
        #pragma unroll
        for (int o = 16; o; o >>= 1) sm += __shfl_xor_sync(FULL, sm, o);
        float lse = mv + logf(sm);
        if (lane < 10) atomicAdd(&sacc[lane], v - lse);
    }
    __syncthreads();
    if (tid < NCLS) atomicAdd(&out[tid], sacc[tid] * (1.0f / (float)NN));
}

// ---------------- launch ----------------
extern "C" void kernel_launch(void* const* d_in, const int* in_sizes, int n_in,
                              void* d_out, int out_size) {
    const float* x  = (const float*)d_in[0];
    const void*  ei = d_in[1];
    const float* W1 = (const float*)d_in[2];
    const float* b1 = (const float*)d_in[3];
    const float* W2 = (const float*)d_in[4];
    const float* b2 = (const float*)d_in[5];
    float* out = (float*)d_out;

    k_init     <<<(NN + 255) / 256, 256>>>(ei, out);       // 0
    k_degree   <<<(NE + 255) / 256, 256>>>(ei);            // 1
    k_scan     <<<NBS, SB>>>();                            // 2
    k_fillx    <<<(NN * 32 + 255) / 256, 256>>>(ei, x);    // 3  <- profiled
    k_gather1  <<<(NN * 32 + 255) / 256, 256>>>();         // 4
    k_gemm12   <<<(NN + 63) / 64, 256>>>(W1, b1, W2);      // 5
    k_gather2f <<<(NN * 32 + 511) / 512, 512>>>(b2, out);  // 6
}

// round 13
// speedup vs baseline: 1.1614x; 1.0097x over previous
#include <cuda_runtime.h>
#include <cuda_fp16.h>
#include <math.h>

#define NN   100000
#define NE   1600000
#define INF  64
#define HIDD 128
#define NCLS 10
#define NCP  12
#define SB   512
#define NBS  ((NN + SB - 1) / SB)    // 196 scan blocks
#define FULL 0xffffffffu

// packed f32x2 helpers
__device__ __forceinline__ unsigned long long f2pk(float lo, float hi) {
    unsigned long long r;
    asm("mov.b64 %0, {%1, %2};" : "=l"(r) : "f"(lo), "f"(hi));
    return r;
}
__device__ __forceinline__ void ffma2(unsigned long long& d,
                                      unsigned long long a,
                                      unsigned long long b) {
    asm("fma.rn.f32x2 %0, %1, %2, %0;" : "+l"(d) : "l"(a), "l"(b));
}
__device__ __forceinline__ float2 f2unpk(unsigned long long v) {
    float lo, hi;
    asm("mov.b64 {%0, %1}, %2;" : "=f"(lo), "=f"(hi) : "l"(v));
    return make_float2(lo, hi);
}

// ---------------- scratch (no allocations allowed) ----------------
__device__ int   g_is64;
__device__ int   g_done;
__device__ int   g_cnt[NN];
__device__ int   g_offs[NN];          // block-local exclusive scan (SB-wide blocks)
__device__ int   g_bsum[NBS];
__device__ int   g_bpre[NBS];
__device__ float g_dinv[NN];
__device__ unsigned short g_rank[NE]; // 3.2 MB : edge's rank within its dest bucket
__device__ int   g_msrc[NE];          // 6.4 MB : CSR src per slot
__device__ __half2 g_xh[NN * 32];     // 12.8 MB : xs = dinv*x in half
__device__ float4 g_agg1[NN * (INF / 4)];   // 25.6 MB
__device__ float g_t2s[NN * NCP];           // 4.8 MB : dinv*(h@W2), stride 12

// ---------------- kernels ----------------

// init (cnt, done, out) + dtype sniff (block 0)
__global__ void k_init(const void* __restrict__ ei_raw, float* __restrict__ out) {
    __shared__ int s_nz;
    int tid = threadIdx.x;
    int i = blockIdx.x * blockDim.x + tid;
    if (i < NN) g_cnt[i] = 0;
    if (i < NCLS) out[i] = 0.0f;
    if (blockIdx.x == 0 && tid == 0) g_done = 0;
    if (tid == 0) s_nz = 0;
    __syncthreads();
    if (blockIdx.x == 0) {
        const unsigned int* w = (const unsigned int*)ei_raw;
        if (w[tid * 2 + 1] != 0u) atomicAdd(&s_nz, 1);
    }
    __syncthreads();
    if (blockIdx.x == 0 && tid == 0) g_is64 = (s_nz == 0) ? 1 : 0;
}

// degree histogram + rank ticket (returning atomic; rank = position in bucket)
__global__ void k_degree(const void* __restrict__ ei_raw) {
    int e = blockIdx.x * blockDim.x + threadIdx.x;
    if (e >= NE) return;
    int c;
    if (g_is64) c = (int)((const long long*)ei_raw)[NE + e];
    else        c = ((const int*)ei_raw)[NE + e];
    c = min(max(c, 0), NN - 1);
    int t = atomicAdd(&g_cnt[c], 1);
    g_rank[e] = (unsigned short)t;
}

// fused scan: block-local exclusive scan + dinv; last block scans block sums
__global__ void k_scan() {
    __shared__ int s[SB];
    __shared__ int isLast;
    int tid = threadIdx.x;
    int i = blockIdx.x * SB + tid;
    int v = (i < NN) ? g_cnt[i] : 0;
    if (i < NN) g_dinv[i] = rsqrtf((float)(v + 1));
    s[tid] = v;
    __syncthreads();
    #pragma unroll
    for (int st = 1; st < SB; st <<= 1) {
        int t = (tid >= st) ? s[tid - st] : 0;
        __syncthreads();
        s[tid] += t;
        __syncthreads();
    }
    if (i < NN) g_offs[i] = s[tid] - v;
    if (tid == SB - 1) {
        g_bsum[blockIdx.x] = s[SB - 1];
        __threadfence();
        int t = atomicAdd(&g_done, 1);
        isLast = (t == (int)gridDim.x - 1);
    }
    __syncthreads();
    if (isLast) {
        int v2 = (tid < NBS) ? g_bsum[tid] : 0;
        s[tid] = v2;
        __syncthreads();
        #pragma unroll
        for (int st = 1; st < SB; st <<= 1) {
            int t = (tid >= st) ? s[tid - st] : 0;
            __syncthreads();
            s[tid] += t;
            __syncthreads();
        }
        if (tid < NBS) g_bpre[tid] = s[tid] - v2;
    }
}

// fused: CSR fill via precomputed rank (NO atomics) + xs = dinv*x -> half
__global__ void k_fillx(const void* __restrict__ ei_raw, const float* __restrict__ x) {
    int i = blockIdx.x * blockDim.x + threadIdx.x;   // NN*32 = 3.2M threads
    if (i < NE) {
        int r, c;
        if (g_is64) {
            const long long* ei = (const long long*)ei_raw;
            r = (int)ei[i];  c = (int)ei[NE + i];
        } else {
            const int* ei = (const int*)ei_raw;
            r = ei[i];       c = ei[NE + i];
        }
        r = min(max(r, 0), NN - 1);
        c = min(max(c, 0), NN - 1);
        int pos = g_offs[c] + g_bpre[c >> 9] + (int)g_rank[i];
        g_msrc[pos] = r;
    }
    if (i < NN * 32) {
        int node = i >> 5;
        float d = g_dinv[node];
        float2 v = ((const float2*)x)[i];
        g_xh[i] = __floats2half2_rn(d * v.x, d * v.y);
    }
}

// layer-1 aggregation: warp per dest node, shfl-chunked meta, MLP=4
__global__ void k_gather1() {
    int wid  = (blockIdx.x * blockDim.x + threadIdx.x) >> 5;
    int lane = threadIdx.x & 31;
    if (wid >= NN) return;
    int d = wid;
    float2 acc = __half22float2(g_xh[d * 32 + lane]);   // self term xs[d]
    float2 acc2 = make_float2(0.f, 0.f);
    int beg = g_offs[d] + g_bpre[d >> 9];
    int deg = g_cnt[d];
    for (int base = 0; base < deg; base += 32) {
        int rem = deg - base;
        int cnt = rem < 32 ? rem : 32;
        int m = (lane < cnt) ? g_msrc[beg + base + lane] : 0;
        int j = 0;
        for (; j + 4 <= cnt; j += 4) {
            int s0 = __shfl_sync(FULL, m, j);
            int s1 = __shfl_sync(FULL, m, j + 1);
            int s2 = __shfl_sync(FULL, m, j + 2);
            int s3 = __shfl_sync(FULL, m, j + 3);
            float2 f0 = __half22float2(g_xh[s0 * 32 + lane]);
            float2 f1 = __half22float2(g_xh[s1 * 32 + lane]);
            float2 f2 = __half22float2(g_xh[s2 * 32 + lane]);
            float2 f3 = __half22float2(g_xh[s3 * 32 + lane]);
            acc.x  += f0.x + f1.x;  acc.y  += f0.y + f1.y;
            acc2.x += f2.x + f3.x;  acc2.y += f2.y + f3.y;
        }
        for (; j < cnt; j++) {
            int src = __shfl_sync(FULL, m, j);
            float2 v = __half22float2(g_xh[src * 32 + lane]);
            acc.x += v.x;  acc.y += v.y;
        }
    }
    float dd = g_dinv[d];
    acc.x = (acc.x + acc2.x) * dd;
    acc.y = (acc.y + acc2.y) * dd;
    ((float2*)g_agg1)[d * 32 + lane] = acc;
}

// fused: h = relu(agg1@W1 + b1) [smem only] ; t2s = dinv*(h@W2)
__global__ void k_gemm12(const float* __restrict__ W1, const float* __restrict__ b1,
                         const float* __restrict__ W2) {
    __shared__ float As[64 * 64];        // A tile / then W2 (1280 floats)
    __shared__ float Bs[64 * 132];       // W1 (64x128) / then h tile stride 132
    int tid = threadIdx.x;
    int bnode = blockIdx.x * 64;

    for (int t = tid; t < (64 * 128) / 4; t += 256)
        ((float4*)Bs)[t] = ((const float4*)W1)[t];
    for (int t = tid; t < 64 * 16; t += 256) {
        int lr = t >> 4, q = t & 15;
        int node = bnode + lr;
        float4 v = (node < NN) ? g_agg1[node * 16 + q]
                               : make_float4(0.f, 0.f, 0.f, 0.f);
        ((float4*)As)[t] = v;
    }
    __syncthreads();

    int tx = tid & 31, ty = tid >> 5;
    unsigned long long a01[8], a23[8];
    #pragma unroll
    for (int i = 0; i < 8; i++) { a01[i] = 0ull; a23[i] = 0ull; }

    #pragma unroll 4
    for (int k = 0; k < 64; k++) {
        float4 bb = ((const float4*)Bs)[k * 32 + tx];
        unsigned long long b01 = f2pk(bb.x, bb.y);
        unsigned long long b23 = f2pk(bb.z, bb.w);
        #pragma unroll
        for (int i = 0; i < 8; i++) {
            float a = As[(ty * 8 + i) * 64 + k];
            unsigned long long aa = f2pk(a, a);
            ffma2(a01[i], aa, b01);
            ffma2(a23[i], aa, b23);
        }
    }
    __syncthreads();

    float4 bias = ((const float4*)b1)[tx];
    #pragma unroll
    for (int i = 0; i < 8; i++) {
        float2 p = f2unpk(a01[i]);
        float2 q = f2unpk(a23[i]);
        float* hrow = &Bs[(ty * 8 + i) * 132 + tx * 4];
        hrow[0] = fmaxf(p.x + bias.x, 0.0f);
        hrow[1] = fmaxf(p.y + bias.y, 0.0f);
        hrow[2] = fmaxf(q.x + bias.z, 0.0f);
        hrow[3] = fmaxf(q.y + bias.w, 0.0f);
    }
    for (int t = tid; t < HIDD * NCLS; t += 256) As[t] = W2[t];
    __syncthreads();

    for (int o = tid; o < 64 * NCLS; o += 256) {
        int ln = o / NCLS, c = o - ln * NCLS;
        int node = bnode + ln;
        if (node < NN) {
            const float* h = &Bs[ln * 132];
            float s = 0.0f;
            #pragma unroll 8
            for (int k = 0; k < HIDD; k++) s = fmaf(h[k], As[k * NCLS + c], s);
            g_t2s[node * NCP + c] = g_dinv[node] * s;
        }
    }
}

// fused: layer-2 gather + bias + self + log_softmax + global mean-reduce
__global__ void k_gather2f(const float* __restrict__ b2, float* __restrict__ out) {
    __shared__ float sacc[NCLS];
    int tid = threadIdx.x;
    if (tid < NCLS) sacc[tid] = 0.0f;
    __syncthreads();
    int wid  = (blockIdx.x * blockDim.x + tid) >> 5;
    int lane = tid & 31;
    if (wid < NN) {
        int d = wid;
        int s = lane / 10;          // 0..2 active
        int c = lane - s * 10;
        float acc = 0.0f, accB = 0.0f;
        int beg = g_offs[d] + g_bpre[d >> 9];
        int deg = g_cnt[d];
        for (int base = 0; base < deg; base += 32) {
            int rem = deg - base;
            int cnt = rem < 32 ? rem : 32;
            int m = (lane < cnt) ? g_msrc[beg + base + lane] : 0;
            int iters = (cnt + 2) / 3;
            int jj = 0;
            for (; jj + 2 <= iters; jj += 2) {
                int j0 = jj * 3 + s;
                int j1 = j0 + 3;
                int s0 = __shfl_sync(FULL, m, j0 < 31 ? j0 : 31);
                int s1 = __shfl_sync(FULL, m, j1 < 31 ? j1 : 31);
                float t0 = 0.f, t1 = 0.f;
                if (s < 3 && j0 < cnt) t0 = g_t2s[s0 * NCP + c];
                if (s < 3 && j1 < cnt) t1 = g_t2s[s1 * NCP + c];
                acc += t0;
                accB += t1;
            }
            for (; jj < iters; jj++) {
                int j = jj * 3 + s;
                int src = __shfl_sync(FULL, m, j < 31 ? j : 31);
                if (s < 3 && j < cnt) acc += g_t2s[src * NCP + c];
            }
        }
        acc += accB;
        float a1 = __shfl_sync(FULL, acc, (lane + 10) & 31);
        float a2 = __shfl_sync(FULL, acc, (lane + 20) & 31);
        float v = 0.0f;
        if (lane < 10) {
            float dd = g_dinv[d];
            v = dd * (acc + a1 + a2 + g_t2s[d * NCP + lane]) + b2[lane];
        }
        float mv = (lane < 10) ? v : -1e30f;
        #pragma unroll
        for (int o = 16; o; o >>= 1) mv = fmaxf(mv, __shfl_xor_sync(FULL, mv, o));
        float ex = (lane < 10) ? expf(v - mv) : 0.0f;
        float sm = ex;
        #pragma unroll
        for (int o = 16; o; o >>= 1) sm += __shfl_xor_sync(FULL, sm, o);
        float lse = mv + logf(sm);
        if (lane < 10) atomicAdd(&sacc[lane], v - lse);
    }
    __syncthreads();
    if (tid < NCLS) atomicAdd(&out[tid], sacc[tid] * (1.0f / (float)NN));
}

// ---------------- launch ----------------
extern "C" void kernel_launch(void* const* d_in, const int* in_sizes, int n_in,
                              void* d_out, int out_size) {
    const float* x  = (const float*)d_in[0];
    const void*  ei = d_in[1];
    const float* W1 = (const float*)d_in[2];
    const float* b1 = (const float*)d_in[3];
    const float* W2 = (const float*)d_in[4];
    const float* b2 = (const float*)d_in[5];
    float* out = (float*)d_out;

    k_init     <<<(NN + 255) / 256, 256>>>(ei, out);       // 0
    k_degree   <<<(NE + 255) / 256, 256>>>(ei);            // 1
    k_scan     <<<NBS, SB>>>();                            // 2
    k_fillx    <<<(NN * 32 + 255) / 256, 256>>>(ei, x);    // 3  <- profiled
    k_gather1  <<<(NN * 32 + 255) / 256, 256>>>();         // 4
    k_gemm12   <<<(NN + 63) / 64, 256>>>(W1, b1, W2);      // 5
    k_gather2f <<<(NN * 32 + 511) / 512, 512>>>(b2, out);  // 6
}